// round 2
// baseline (speedup 1.0000x reference)
#include <cuda_runtime.h>

#define NJ 17
#define DM 128
#define NEDGE 49
#define NT 320
#define NWARP 10
#define SMEM_FLOATS 17780
#define SMEM_BYTES (SMEM_FLOATS * 4)

// Skeleton adjacency (incl. self loops), CSR over rows (softmax axis = neighbor j)
__device__ __constant__ int c_row_start[18] =
    {0,4,7,10,12,15,18,20,23,28,31,33,36,39,41,44,47,49};
__device__ __constant__ signed char c_nbr[NEDGE] = {
    0,1,4,7,  0,1,2,  1,2,3,  2,3,  0,4,5,  4,5,6,  5,6,  0,7,8,
    7,8,9,11,14,  8,9,10,  9,10,  8,11,12,  11,12,13,  12,13,
    8,14,15,  14,15,16,  15,16};
__device__ __constant__ signed char c_erow[NEDGE] = {
    0,0,0,0,  1,1,1,  2,2,2,  3,3,  4,4,4,  5,5,5,  6,6,  7,7,7,
    8,8,8,8,8,  9,9,9,  10,10,  11,11,11,  12,12,12,  13,13,
    14,14,14,  15,15,15,  16,16};

__device__ __forceinline__ float warp_sum(float v) {
#pragma unroll
    for (int o = 16; o; o >>= 1) v += __shfl_xor_sync(0xffffffffu, v, o);
    return v;
}

__device__ __forceinline__ unsigned long long pack2(float x, float y) {
    unsigned long long r;
    asm("mov.b64 %0, {%1, %2};" : "=l"(r) : "f"(x), "f"(y));
    return r;
}

__device__ __forceinline__ void ffma2(unsigned long long& d,
                                      unsigned long long a,
                                      unsigned long long b) {
    asm("fma.rn.f32x2 %0, %1, %2, %0;" : "+l"(d) : "l"(a), "l"(b));
}

__device__ __forceinline__ float unpack_add(unsigned long long p) {
    float lo, hi;
    asm("mov.b64 {%0, %1}, %2;" : "=f"(lo), "=f"(hi) : "l"(p));
    return lo + hi;
}

__global__ __launch_bounds__(NT, 2)
void spatial_appnp_kernel(
    const float* __restrict__ x,
    const float* __restrict__ og, const float* __restrict__ ob,
    const float* __restrict__ lg, const float* __restrict__ lb,
    const float* __restrict__ aw, const float* __restrict__ ab,
    const float* __restrict__ w1, const float* __restrict__ b1,
    const float* __restrict__ w2, const float* __restrict__ b2,
    const float* __restrict__ psw, const float* __restrict__ psb,
    const float* __restrict__ vw, const float* __restrict__ vb,
    float* __restrict__ out)
{
    extern __shared__ float sm[];
    float* XN   = sm;              // 17*128 = 2176
    float* XS   = sm + 2176;       // current x
    float* X0   = sm + 4352;       // x0
    float* LRV  = sm + 6528;       // 17*640 = 10880 (l | r | v)
    float* SC   = sm + 17408;      // 2*49 scores
    float* SKIP = sm + 17506;      // 17
    float* PSW  = sm + 17524;      // 128
    float* ALW  = sm + 17652;      // 128

    const int tid  = threadIdx.x;
    const int warp = tid >> 5;
    const int lane = tid & 31;
    const long frame = blockIdx.x;
    const float* xg  = x   + frame * (long)(NJ * DM);
    float*       outg = out + frame * (long)(NJ * DM);

    if (tid < 128) { PSW[tid] = psw[tid]; ALW[tid] = aw[tid]; }

    // ---- outer LayerNorm -> XS and X0 ----
    for (int r = warp; r < NJ; r += NWARP) {
        float v[4];
#pragma unroll
        for (int q = 0; q < 4; q++) v[q] = xg[r * DM + lane + 32 * q];
        float m = warp_sum(v[0] + v[1] + v[2] + v[3]) * (1.0f / 128.0f);
        float ss = 0.f;
#pragma unroll
        for (int q = 0; q < 4; q++) { float d = v[q] - m; ss += d * d; }
        ss = warp_sum(ss);
        float rstd = rsqrtf(ss * (1.0f / 128.0f) + 1e-5f);
#pragma unroll
        for (int q = 0; q < 4; q++) {
            int k = lane + 32 * q;
            float y = (v[q] - m) * rstd * og[k] + ob[k];
            XS[r * DM + k] = y;
            X0[r * DM + k] = y;
        }
    }

    // ---- per-thread GEMM column mapping: c0 = tid, c1 = tid + 320 ----
    const float *base0, *base1;
    int s0, s1;
    float bi0, bi1;
    {
        int c0 = tid;
        if (c0 < 256) { base0 = w1 + c0;        s0 = 256; bi0 = b1[c0]; }
        else          { base0 = w2 + (c0 - 256); s0 = 256; bi0 = b2[c0 - 256]; }
        int c1 = tid + NT;
        if (c1 < 512) { base1 = w2 + (c1 - 256); s1 = 256; bi1 = b2[c1 - 256]; }
        else          { base1 = vw + (c1 - 512); s1 = 128; bi1 = vb[c1 - 512]; }
    }
    const float abv = ab[0];
    __syncthreads();

    for (int it = 0; it < 4; it++) {
        // ---- inner LayerNorm -> XN, plus skip gate ----
        for (int r = warp; r < NJ; r += NWARP) {
            float v[4];
#pragma unroll
            for (int q = 0; q < 4; q++) v[q] = XS[r * DM + lane + 32 * q];
            float m = warp_sum(v[0] + v[1] + v[2] + v[3]) * (1.0f / 128.0f);
            float ss = 0.f;
#pragma unroll
            for (int q = 0; q < 4; q++) { float d = v[q] - m; ss += d * d; }
            ss = warp_sum(ss);
            float rstd = rsqrtf(ss * (1.0f / 128.0f) + 1e-5f);
            float ad = 0.f;
#pragma unroll
            for (int q = 0; q < 4; q++) {
                int k = lane + 32 * q;
                float y = (v[q] - m) * rstd * lg[k] + lb[k];
                XN[r * DM + k] = y;
                ad = fmaf(y, ALW[k], ad);
            }
            ad = warp_sum(ad);
            if (lane == 0) SKIP[r] = 1.0f / (1.0f + expf(-(ad + abv)));
        }
        __syncthreads();

        // ---- fused GEMM: LRV[17][640] = XN @ [w1 | w2 | v_w] + bias ----
        {
            unsigned long long acc0[NJ], acc1[NJ];
#pragma unroll
            for (int i = 0; i < NJ; i++) { acc0[i] = 0ull; acc1[i] = 0ull; }
            const float* q0 = base0;
            const float* q1 = base1;
#pragma unroll 1
            for (int k = 0; k < DM; k += 2) {
                float a0 = q0[0], a1 = q0[s0]; q0 += 2 * s0;
                float c0 = q1[0], c1 = q1[s1]; q1 += 2 * s1;
                unsigned long long wp0 = pack2(a0, a1);
                unsigned long long wp1 = pack2(c0, c1);
#pragma unroll
                for (int i = 0; i < NJ; i++) {
                    float2 xv = *reinterpret_cast<const float2*>(&XN[i * DM + k]);
                    unsigned long long xp = pack2(xv.x, xv.y);
                    ffma2(acc0[i], xp, wp0);
                    ffma2(acc1[i], xp, wp1);
                }
            }
#pragma unroll
            for (int i = 0; i < NJ; i++) {
                LRV[i * 640 + tid]      = unpack_add(acc0[i]) + bi0;
                LRV[i * 640 + tid + NT] = unpack_add(acc1[i]) + bi1;
            }
        }
        __syncthreads();

        // ---- attention scores: only the 49 adjacent pairs, 2 heads ----
        for (int t = warp; t < 2 * NEDGE; t += NWARP) {
            int h = (t >= NEDGE);
            int e = t - h * NEDGE;
            int i = c_erow[e];
            int j = c_nbr[e];
            const float* lp = LRV + i * 640 + h * 128;
            const float* rp = LRV + j * 640 + 256 + h * 128;
            float acc = 0.f;
#pragma unroll
            for (int q = 0; q < 4; q++) {
                int d = lane + 32 * q;
                float u  = lp[d] + rp[d];
                float lr = fmaxf(u, 0.2f * u);   // leaky_relu(u, 0.2)
                acc = fmaf(lr, PSW[d], acc);
            }
            acc = warp_sum(acc);
            if (lane == 0) SC[t] = acc;          // ps_b dropped: softmax-invariant
        }
        __syncthreads();

        // ---- softmax over each row's neighbor list (34 tasks) ----
        if (tid < 34) {
            int h = (tid >= NJ);
            int i = tid - h * NJ;
            int rs = c_row_start[i], re = c_row_start[i + 1];
            float m = -1e30f;
            for (int e = rs; e < re; e++) m = fmaxf(m, SC[h * NEDGE + e]);
            float s = 0.f;
            for (int e = rs; e < re; e++) s += expf(SC[h * NEDGE + e] - m);
            float inv = 1.0f / s;
            for (int e = rs; e < re; e++)
                SC[h * NEDGE + e] = expf(SC[h * NEDGE + e] - m) * inv;
        }
        __syncthreads();

        // ---- sparse aggregate + exact GELU + skip mix -> XS ----
        for (int idx = tid; idx < NJ * DM; idx += NT) {
            int j = idx >> 7, c = idx & 127;
            int h = c >> 6,  d = c & 63;
            int rs = c_row_start[j], re = c_row_start[j + 1];
            float acc = 0.f;
            for (int e = rs; e < re; e++)
                acc = fmaf(SC[h * NEDGE + e],
                           LRV[(int)c_nbr[e] * 640 + 512 + h * 64 + d], acc);
            float g  = 0.5f * acc * (1.0f + erff(acc * 0.70710678118654752f));
            float sk = SKIP[j];
            XS[idx] = (1.0f - sk) * g + sk * X0[idx];
        }
        __syncthreads();
    }

    for (int idx = tid; idx < NJ * DM; idx += NT)
        outg[idx] = XS[idx];
}

extern "C" void kernel_launch(void* const* d_in, const int* in_sizes, int n_in,
                              void* d_out, int out_size) {
    const float* x   = (const float*)d_in[0];
    const float* og  = (const float*)d_in[1];
    const float* ob  = (const float*)d_in[2];
    const float* lg  = (const float*)d_in[3];
    const float* lb  = (const float*)d_in[4];
    const float* aw  = (const float*)d_in[5];
    const float* ab  = (const float*)d_in[6];
    const float* w1  = (const float*)d_in[7];
    const float* b1  = (const float*)d_in[8];
    const float* w2  = (const float*)d_in[9];
    const float* b2  = (const float*)d_in[10];
    const float* psw = (const float*)d_in[11];
    const float* psb = (const float*)d_in[12];
    const float* vw  = (const float*)d_in[13];
    const float* vb  = (const float*)d_in[14];
    float* out = (float*)d_out;

    int frames = in_sizes[0] / (NJ * DM);   // 16*243 = 3888

    cudaFuncSetAttribute(spatial_appnp_kernel,
                         cudaFuncAttributeMaxDynamicSharedMemorySize, SMEM_BYTES);

    spatial_appnp_kernel<<<frames, NT, SMEM_BYTES>>>(
        x, og, ob, lg, lb, aw, ab, w1, b1, w2, b2, psw, psb, vw, vb, out);
}

// round 3
// speedup vs baseline: 1.0967x; 1.0967x over previous
#include <cuda_runtime.h>

#define NJ 17
#define DM 128
#define NCOL 640
#define NEDGE 49
#define NT 320
#define NWARP 10
#define SMEM_FLOATS 17780
#define SMEM_BYTES (SMEM_FLOATS * 4)

// Interleaved transposed weights: g_wt[(q*NCOL + c)*4 + j] = W[k=4q+j][c]
// where W = [w1 | w2 | v_w] column-concat. g_bc = [b1 | b2 | v_b].
__device__ float g_wt[32 * NCOL * 4];
__device__ float g_bc[NCOL];

// Skeleton adjacency (incl. self loops), CSR over rows (softmax axis = neighbor j)
__device__ __constant__ int c_row_start[18] =
    {0,4,7,10,12,15,18,20,23,28,31,33,36,39,41,44,47,49};
__device__ __constant__ signed char c_nbr[NEDGE] = {
    0,1,4,7,  0,1,2,  1,2,3,  2,3,  0,4,5,  4,5,6,  5,6,  0,7,8,
    7,8,9,11,14,  8,9,10,  9,10,  8,11,12,  11,12,13,  12,13,
    8,14,15,  14,15,16,  15,16};
__device__ __constant__ signed char c_erow[NEDGE] = {
    0,0,0,0,  1,1,1,  2,2,2,  3,3,  4,4,4,  5,5,5,  6,6,  7,7,7,
    8,8,8,8,8,  9,9,9,  10,10,  11,11,11,  12,12,12,  13,13,
    14,14,14,  15,15,15,  16,16};

__device__ __forceinline__ float warp_sum(float v) {
#pragma unroll
    for (int o = 16; o; o >>= 1) v += __shfl_xor_sync(0xffffffffu, v, o);
    return v;
}

__device__ __forceinline__ void ffma2(unsigned long long& d,
                                      unsigned long long a,
                                      unsigned long long b) {
    asm("fma.rn.f32x2 %0, %1, %2, %0;" : "+l"(d) : "l"(a), "l"(b));
}

__device__ __forceinline__ float unpack_add(unsigned long long p) {
    float lo, hi;
    asm("mov.b64 {%0, %1}, %2;" : "=f"(lo), "=f"(hi) : "l"(p));
    return lo + hi;
}

// ---------------- prologue: weight transpose/interleave ----------------
__global__ void prep_kernel(const float* __restrict__ w1, const float* __restrict__ b1,
                            const float* __restrict__ w2, const float* __restrict__ b2,
                            const float* __restrict__ vw, const float* __restrict__ vb)
{
    int idx = blockIdx.x * blockDim.x + threadIdx.x;
    if (idx < 32 * NCOL) {
        int q = idx / NCOL, c = idx % NCOL;
        const float* src; int stride;
        if (c < 256)      { src = w1 + c;         stride = 256; }
        else if (c < 512) { src = w2 + (c - 256); stride = 256; }
        else              { src = vw + (c - 512); stride = 128; }
        float4 v;
        v.x = src[(4 * q + 0) * stride];
        v.y = src[(4 * q + 1) * stride];
        v.z = src[(4 * q + 2) * stride];
        v.w = src[(4 * q + 3) * stride];
        *reinterpret_cast<float4*>(&g_wt[idx * 4]) = v;
    }
    if (idx < NCOL) {
        g_bc[idx] = (idx < 256) ? b1[idx]
                  : (idx < 512) ? b2[idx - 256]
                                : vb[idx - 512];
    }
}

// ---------------- main fused kernel ----------------
__global__ __launch_bounds__(NT, 2)
void spatial_appnp_kernel(
    const float* __restrict__ x,
    const float* __restrict__ og, const float* __restrict__ ob,
    const float* __restrict__ lg, const float* __restrict__ lb,
    const float* __restrict__ aw, const float* __restrict__ ab,
    const float* __restrict__ psw,
    float* __restrict__ out)
{
    extern __shared__ float sm[];
    float* XN   = sm;              // 17*128
    float* XS   = sm + 2176;       // current x
    float* X0   = sm + 4352;       // x0
    float* LRV  = sm + 6528;       // 17*640 (l | r | v)
    float* SC   = sm + 17408;      // 2*49 scores
    float* SKIP = sm + 17506;      // 17
    float* PSW  = sm + 17524;      // 128
    float* ALW  = sm + 17652;      // 128

    const int tid  = threadIdx.x;
    const int warp = tid >> 5;
    const int lane = tid & 31;
    const long frame = blockIdx.x;
    const float* xg   = x   + frame * (long)(NJ * DM);
    float*       outg = out + frame * (long)(NJ * DM);

    if (tid < 128) { PSW[tid] = psw[tid]; ALW[tid] = aw[tid]; }

    // ---- outer LayerNorm -> XS and X0 ----
    for (int r = warp; r < NJ; r += NWARP) {
        float v[4];
#pragma unroll
        for (int q = 0; q < 4; q++) v[q] = xg[r * DM + lane + 32 * q];
        float m = warp_sum(v[0] + v[1] + v[2] + v[3]) * (1.0f / 128.0f);
        float ss = 0.f;
#pragma unroll
        for (int q = 0; q < 4; q++) { float d = v[q] - m; ss += d * d; }
        ss = warp_sum(ss);
        float rstd = rsqrtf(ss * (1.0f / 128.0f) + 1e-5f);
#pragma unroll
        for (int q = 0; q < 4; q++) {
            int k = lane + 32 * q;
            float y = (v[q] - m) * rstd * og[k] + ob[k];
            XS[r * DM + k] = y;
            X0[r * DM + k] = y;
        }
    }

    const float bi0 = g_bc[tid];
    const float bi1 = g_bc[tid + NT];
    const float abv = ab[0];
    const float* wp0 = g_wt + tid * 4;
    const float* wp1 = g_wt + (tid + NT) * 4;
    __syncthreads();

    for (int it = 0; it < 4; it++) {
        // ---- inner LayerNorm -> XN, plus skip gate ----
        for (int r = warp; r < NJ; r += NWARP) {
            float v[4];
#pragma unroll
            for (int q = 0; q < 4; q++) v[q] = XS[r * DM + lane + 32 * q];
            float m = warp_sum(v[0] + v[1] + v[2] + v[3]) * (1.0f / 128.0f);
            float ss = 0.f;
#pragma unroll
            for (int q = 0; q < 4; q++) { float d = v[q] - m; ss += d * d; }
            ss = warp_sum(ss);
            float rstd = rsqrtf(ss * (1.0f / 128.0f) + 1e-5f);
            float ad = 0.f;
#pragma unroll
            for (int q = 0; q < 4; q++) {
                int k = lane + 32 * q;
                float y = (v[q] - m) * rstd * lg[k] + lb[k];
                XN[r * DM + k] = y;
                ad = fmaf(y, ALW[k], ad);
            }
            ad = warp_sum(ad);
            if (lane == 0) SKIP[r] = 1.0f / (1.0f + __expf(-(ad + abv)));
        }
        __syncthreads();

        // ---- fused GEMM: LRV[17][640] = XN @ [w1 | w2 | v_w] + bias ----
        {
            unsigned long long acc0[NJ], acc1[NJ];
#pragma unroll
            for (int i = 0; i < NJ; i++) { acc0[i] = 0ull; acc1[i] = 0ull; }
#pragma unroll 2
            for (int q = 0; q < 32; q++) {
                // coalesced LDG.128: pairs land directly as f32x2 operands
                longlong2 w0 = *reinterpret_cast<const longlong2*>(wp0 + (long)q * NCOL * 4);
                longlong2 w1v = *reinterpret_cast<const longlong2*>(wp1 + (long)q * NCOL * 4);
#pragma unroll
                for (int i = 0; i < NJ; i++) {
                    longlong2 xv = *reinterpret_cast<const longlong2*>(&XN[i * DM + 4 * q]);
                    ffma2(acc0[i], (unsigned long long)xv.x, (unsigned long long)w0.x);
                    ffma2(acc0[i], (unsigned long long)xv.y, (unsigned long long)w0.y);
                    ffma2(acc1[i], (unsigned long long)xv.x, (unsigned long long)w1v.x);
                    ffma2(acc1[i], (unsigned long long)xv.y, (unsigned long long)w1v.y);
                }
            }
#pragma unroll
            for (int i = 0; i < NJ; i++) {
                LRV[i * 640 + tid]      = unpack_add(acc0[i]) + bi0;
                LRV[i * 640 + tid + NT] = unpack_add(acc1[i]) + bi1;
            }
        }
        __syncthreads();

        // ---- attention scores: only the 49 adjacent pairs, 2 heads ----
        for (int t = warp; t < 2 * NEDGE; t += NWARP) {
            int h = (t >= NEDGE);
            int e = t - h * NEDGE;
            int i = c_erow[e];
            int j = c_nbr[e];
            const float* lp = LRV + i * 640 + h * 128;
            const float* rp = LRV + j * 640 + 256 + h * 128;
            float acc = 0.f;
#pragma unroll
            for (int q = 0; q < 4; q++) {
                int d = lane + 32 * q;
                float u  = lp[d] + rp[d];
                float lr = fmaxf(u, 0.2f * u);   // leaky_relu(u, 0.2)
                acc = fmaf(lr, PSW[d], acc);
            }
            acc = warp_sum(acc);
            if (lane == 0) SC[t] = acc;          // ps_b dropped: softmax-invariant
        }
        __syncthreads();

        // ---- softmax over each row's neighbor list (34 tasks) ----
        if (tid < 34) {
            int h = (tid >= NJ);
            int i = tid - h * NJ;
            int rs = c_row_start[i], re = c_row_start[i + 1];
            float m = -1e30f;
            for (int e = rs; e < re; e++) m = fmaxf(m, SC[h * NEDGE + e]);
            float s = 0.f;
            for (int e = rs; e < re; e++) s += __expf(SC[h * NEDGE + e] - m);
            float inv = 1.0f / s;
            for (int e = rs; e < re; e++)
                SC[h * NEDGE + e] = __expf(SC[h * NEDGE + e] - m) * inv;
        }
        __syncthreads();

        // ---- sparse aggregate + exact GELU + skip mix -> XS ----
        for (int idx = tid; idx < NJ * DM; idx += NT) {
            int j = idx >> 7, c = idx & 127;
            int h = c >> 6,  d = c & 63;
            int rs = c_row_start[j], re = c_row_start[j + 1];
            float acc = 0.f;
            for (int e = rs; e < re; e++)
                acc = fmaf(SC[h * NEDGE + e],
                           LRV[(int)c_nbr[e] * 640 + 512 + h * 64 + d], acc);
            float g  = 0.5f * acc * (1.0f + erff(acc * 0.70710678118654752f));
            float sk = SKIP[j];
            XS[idx] = (1.0f - sk) * g + sk * X0[idx];
        }
        __syncthreads();
    }

    for (int idx = tid * 4; idx < NJ * DM; idx += NT * 4)
        *reinterpret_cast<float4*>(&outg[idx]) =
            *reinterpret_cast<const float4*>(&XS[idx]);
}

extern "C" void kernel_launch(void* const* d_in, const int* in_sizes, int n_in,
                              void* d_out, int out_size) {
    const float* x   = (const float*)d_in[0];
    const float* og  = (const float*)d_in[1];
    const float* ob  = (const float*)d_in[2];
    const float* lg  = (const float*)d_in[3];
    const float* lb  = (const float*)d_in[4];
    const float* aw  = (const float*)d_in[5];
    const float* ab  = (const float*)d_in[6];
    const float* w1  = (const float*)d_in[7];
    const float* b1  = (const float*)d_in[8];
    const float* w2  = (const float*)d_in[9];
    const float* b2  = (const float*)d_in[10];
    const float* psw = (const float*)d_in[11];
    const float* vw  = (const float*)d_in[13];
    const float* vb  = (const float*)d_in[14];
    float* out = (float*)d_out;

    int frames = in_sizes[0] / (NJ * DM);   // 16*243 = 3888

    prep_kernel<<<(32 * NCOL + 255) / 256, 256>>>(w1, b1, w2, b2, vw, vb);

    cudaFuncSetAttribute(spatial_appnp_kernel,
                         cudaFuncAttributeMaxDynamicSharedMemorySize, SMEM_BYTES);

    spatial_appnp_kernel<<<frames, NT, SMEM_BYTES>>>(
        x, og, ob, lg, lb, aw, ab, psw, out);
}

// round 4
// speedup vs baseline: 1.2185x; 1.1111x over previous
#include <cuda_runtime.h>

#define NJ 17
#define DM 128
#define NCOL 640
#define NEDGE 49
#define NT 320
#define NWARP 10
#define SMEM_FLOATS 17780
#define SMEM_BYTES (SMEM_FLOATS * 4)

// Interleaved transposed weights: g_wt[q*NCOL + c] = float4 of W[k=4q..4q+3][c]
// where W = [w1 | w2 | v_w] column-concat. g_bc = [b1 | b2 | v_b].
__device__ __align__(16) float4 g_wt[32 * NCOL];
__device__ float g_bc[NCOL];

// Skeleton adjacency (incl. self loops), CSR over rows (softmax axis = neighbor j)
__device__ __constant__ int c_row_start[18] =
    {0,4,7,10,12,15,18,20,23,28,31,33,36,39,41,44,47,49};
__device__ __constant__ signed char c_nbr[NEDGE] = {
    0,1,4,7,  0,1,2,  1,2,3,  2,3,  0,4,5,  4,5,6,  5,6,  0,7,8,
    7,8,9,11,14,  8,9,10,  9,10,  8,11,12,  11,12,13,  12,13,
    8,14,15,  14,15,16,  15,16};
__device__ __constant__ signed char c_erow[NEDGE] = {
    0,0,0,0,  1,1,1,  2,2,2,  3,3,  4,4,4,  5,5,5,  6,6,  7,7,7,
    8,8,8,8,8,  9,9,9,  10,10,  11,11,11,  12,12,12,  13,13,
    14,14,14,  15,15,15,  16,16};

__device__ __forceinline__ float warp_sum(float v) {
#pragma unroll
    for (int o = 16; o; o >>= 1) v += __shfl_xor_sync(0xffffffffu, v, o);
    return v;
}

__device__ __forceinline__ void ffma2(unsigned long long& d,
                                      unsigned long long a,
                                      unsigned long long b) {
    asm("fma.rn.f32x2 %0, %1, %2, %0;" : "+l"(d) : "l"(a), "l"(b));
}

__device__ __forceinline__ float unpack_add(unsigned long long p) {
    float lo, hi;
    asm("mov.b64 {%0, %1}, %2;" : "=f"(lo), "=f"(hi) : "l"(p));
    return lo + hi;
}

// ---------------- prologue: weight transpose/interleave ----------------
__global__ void prep_kernel(const float* __restrict__ w1, const float* __restrict__ b1,
                            const float* __restrict__ w2, const float* __restrict__ b2,
                            const float* __restrict__ vw, const float* __restrict__ vb)
{
    int idx = blockIdx.x * blockDim.x + threadIdx.x;
    if (idx < 32 * NCOL) {
        int q = idx / NCOL, c = idx % NCOL;
        const float* src; int stride;
        if (c < 256)      { src = w1 + c;         stride = 256; }
        else if (c < 512) { src = w2 + (c - 256); stride = 256; }
        else              { src = vw + (c - 512); stride = 128; }
        float4 v;
        v.x = src[(4 * q + 0) * stride];
        v.y = src[(4 * q + 1) * stride];
        v.z = src[(4 * q + 2) * stride];
        v.w = src[(4 * q + 3) * stride];
        g_wt[idx] = v;
    }
    if (idx < NCOL) {
        g_bc[idx] = (idx < 256) ? b1[idx]
                  : (idx < 512) ? b2[idx - 256]
                                : vb[idx - 512];
    }
}

// ---- GEMM inner: thread owns 4 columns {ct, ct+160, ct+320, ct+480},
//      NR rows starting at r0. x loads amortized over 4 columns. ----
template<int NR>
__device__ __forceinline__ void gemm_rows(const float* __restrict__ XN,
                                          float* __restrict__ LRV,
                                          int r0, int ct,
                                          float bi0, float bi1, float bi2, float bi3)
{
    unsigned long long acc[4][NR];
#pragma unroll
    for (int p = 0; p < 4; p++)
#pragma unroll
        for (int r = 0; r < NR; r++) acc[p][r] = 0ull;

    const float4* wb = g_wt + ct;
#pragma unroll 1
    for (int q = 0; q < 32; q++) {
        // 4 coalesced LDG.128: each instruction reads a contiguous 512B run
        longlong2 w0 = *reinterpret_cast<const longlong2*>(wb + q * NCOL + 0);
        longlong2 w1v = *reinterpret_cast<const longlong2*>(wb + q * NCOL + 160);
        longlong2 w2v = *reinterpret_cast<const longlong2*>(wb + q * NCOL + 320);
        longlong2 w3v = *reinterpret_cast<const longlong2*>(wb + q * NCOL + 480);
#pragma unroll
        for (int r = 0; r < NR; r++) {
            longlong2 xv = *reinterpret_cast<const longlong2*>(&XN[(r0 + r) * DM + 4 * q]);
            ffma2(acc[0][r], (unsigned long long)xv.x, (unsigned long long)w0.x);
            ffma2(acc[0][r], (unsigned long long)xv.y, (unsigned long long)w0.y);
            ffma2(acc[1][r], (unsigned long long)xv.x, (unsigned long long)w1v.x);
            ffma2(acc[1][r], (unsigned long long)xv.y, (unsigned long long)w1v.y);
            ffma2(acc[2][r], (unsigned long long)xv.x, (unsigned long long)w2v.x);
            ffma2(acc[2][r], (unsigned long long)xv.y, (unsigned long long)w2v.y);
            ffma2(acc[3][r], (unsigned long long)xv.x, (unsigned long long)w3v.x);
            ffma2(acc[3][r], (unsigned long long)xv.y, (unsigned long long)w3v.y);
        }
    }
#pragma unroll
    for (int r = 0; r < NR; r++) {
        float* o = LRV + (r0 + r) * NCOL + ct;
        o[0]   = unpack_add(acc[0][r]) + bi0;
        o[160] = unpack_add(acc[1][r]) + bi1;
        o[320] = unpack_add(acc[2][r]) + bi2;
        o[480] = unpack_add(acc[3][r]) + bi3;
    }
}

// ---------------- main fused kernel ----------------
__global__ __launch_bounds__(NT, 2)
void spatial_appnp_kernel(
    const float* __restrict__ x,
    const float* __restrict__ og, const float* __restrict__ ob,
    const float* __restrict__ lg, const float* __restrict__ lb,
    const float* __restrict__ aw, const float* __restrict__ ab,
    const float* __restrict__ psw,
    float* __restrict__ out)
{
    extern __shared__ float sm[];
    float* XN   = sm;              // 17*128
    float* XS   = sm + 2176;       // current x
    float* X0   = sm + 4352;       // x0
    float* LRV  = sm + 6528;       // 17*640 (l | r | v)
    float* SC   = sm + 17408;      // 2*49 scores
    float* SKIP = sm + 17506;      // 17
    float* PSW  = sm + 17524;      // 128
    float* ALW  = sm + 17652;      // 128

    const int tid  = threadIdx.x;
    const int warp = tid >> 5;
    const int lane = tid & 31;
    const long frame = blockIdx.x;
    const float* xg   = x   + frame * (long)(NJ * DM);
    float*       outg = out + frame * (long)(NJ * DM);

    if (tid < 128) { PSW[tid] = psw[tid]; ALW[tid] = aw[tid]; }

    // ---- outer LayerNorm -> XS and X0 ----
    for (int r = warp; r < NJ; r += NWARP) {
        float v[4];
#pragma unroll
        for (int q = 0; q < 4; q++) v[q] = xg[r * DM + lane + 32 * q];
        float m = warp_sum(v[0] + v[1] + v[2] + v[3]) * (1.0f / 128.0f);
        float ss = 0.f;
#pragma unroll
        for (int q = 0; q < 4; q++) { float d = v[q] - m; ss += d * d; }
        ss = warp_sum(ss);
        float rstd = rsqrtf(ss * (1.0f / 128.0f) + 1e-5f);
#pragma unroll
        for (int q = 0; q < 4; q++) {
            int k = lane + 32 * q;
            float y = (v[q] - m) * rstd * og[k] + ob[k];
            XS[r * DM + k] = y;
            X0[r * DM + k] = y;
        }
    }

    // ---- thread -> (row-group, column) mapping for the GEMM ----
    const int rg = (tid >= 160);          // 0: rows 0-8, 1: rows 9-16
    const int ct = tid - rg * 160;        // 0..159
    const int r0 = rg ? 9 : 0;
    const float bi0 = g_bc[ct];
    const float bi1 = g_bc[ct + 160];
    const float bi2 = g_bc[ct + 320];
    const float bi3 = g_bc[ct + 480];
    const float abv = ab[0];
    __syncthreads();

    for (int it = 0; it < 4; it++) {
        // ---- inner LayerNorm -> XN, plus skip gate ----
        for (int r = warp; r < NJ; r += NWARP) {
            float v[4];
#pragma unroll
            for (int q = 0; q < 4; q++) v[q] = XS[r * DM + lane + 32 * q];
            float m = warp_sum(v[0] + v[1] + v[2] + v[3]) * (1.0f / 128.0f);
            float ss = 0.f;
#pragma unroll
            for (int q = 0; q < 4; q++) { float d = v[q] - m; ss += d * d; }
            ss = warp_sum(ss);
            float rstd = rsqrtf(ss * (1.0f / 128.0f) + 1e-5f);
            float ad = 0.f;
#pragma unroll
            for (int q = 0; q < 4; q++) {
                int k = lane + 32 * q;
                float y = (v[q] - m) * rstd * lg[k] + lb[k];
                XN[r * DM + k] = y;
                ad = fmaf(y, ALW[k], ad);
            }
            ad = warp_sum(ad);
            if (lane == 0) SKIP[r] = 1.0f / (1.0f + __expf(-(ad + abv)));
        }
        __syncthreads();

        // ---- fused GEMM: LRV[17][640] = XN @ [w1 | w2 | v_w] + bias ----
        if (rg == 0) gemm_rows<9>(XN, LRV, r0, ct, bi0, bi1, bi2, bi3);
        else         gemm_rows<8>(XN, LRV, r0, ct, bi0, bi1, bi2, bi3);
        __syncthreads();

        // ---- attention scores: only the 49 adjacent pairs, 2 heads ----
        for (int t = warp; t < 2 * NEDGE; t += NWARP) {
            int h = (t >= NEDGE);
            int e = t - h * NEDGE;
            int i = c_erow[e];
            int j = c_nbr[e];
            const float* lp = LRV + i * 640 + h * 128;
            const float* rp = LRV + j * 640 + 256 + h * 128;
            float acc = 0.f;
#pragma unroll
            for (int q = 0; q < 4; q++) {
                int d = lane + 32 * q;
                float u  = lp[d] + rp[d];
                float lr = fmaxf(u, 0.2f * u);   // leaky_relu(u, 0.2)
                acc = fmaf(lr, PSW[d], acc);
            }
            acc = warp_sum(acc);
            if (lane == 0) SC[t] = acc;          // ps_b dropped: softmax-invariant
        }
        __syncthreads();

        // ---- softmax over each row's neighbor list (34 tasks) ----
        if (tid < 34) {
            int h = (tid >= NJ);
            int i = tid - h * NJ;
            int rs = c_row_start[i], re = c_row_start[i + 1];
            float m = -1e30f;
            for (int e = rs; e < re; e++) m = fmaxf(m, SC[h * NEDGE + e]);
            float s = 0.f;
            for (int e = rs; e < re; e++) s += __expf(SC[h * NEDGE + e] - m);
            float inv = 1.0f / s;
            for (int e = rs; e < re; e++)
                SC[h * NEDGE + e] = __expf(SC[h * NEDGE + e] - m) * inv;
        }
        __syncthreads();

        // ---- sparse aggregate + exact GELU + skip mix -> XS ----
        for (int idx = tid; idx < NJ * DM; idx += NT) {
            int j = idx >> 7, c = idx & 127;
            int h = c >> 6,  d = c & 63;
            int rs = c_row_start[j], re = c_row_start[j + 1];
            float acc = 0.f;
            for (int e = rs; e < re; e++)
                acc = fmaf(SC[h * NEDGE + e],
                           LRV[(int)c_nbr[e] * 640 + 512 + h * 64 + d], acc);
            float g  = 0.5f * acc * (1.0f + erff(acc * 0.70710678118654752f));
            float sk = SKIP[j];
            XS[idx] = (1.0f - sk) * g + sk * X0[idx];
        }
        __syncthreads();
    }

    for (int idx = tid * 4; idx < NJ * DM; idx += NT * 4)
        *reinterpret_cast<float4*>(&outg[idx]) =
            *reinterpret_cast<const float4*>(&XS[idx]);
}

extern "C" void kernel_launch(void* const* d_in, const int* in_sizes, int n_in,
                              void* d_out, int out_size) {
    const float* x   = (const float*)d_in[0];
    const float* og  = (const float*)d_in[1];
    const float* ob  = (const float*)d_in[2];
    const float* lg  = (const float*)d_in[3];
    const float* lb  = (const float*)d_in[4];
    const float* aw  = (const float*)d_in[5];
    const float* ab  = (const float*)d_in[6];
    const float* w1  = (const float*)d_in[7];
    const float* b1  = (const float*)d_in[8];
    const float* w2  = (const float*)d_in[9];
    const float* b2  = (const float*)d_in[10];
    const float* psw = (const float*)d_in[11];
    const float* vw  = (const float*)d_in[13];
    const float* vb  = (const float*)d_in[14];
    float* out = (float*)d_out;

    int frames = in_sizes[0] / (NJ * DM);   // 16*243 = 3888

    prep_kernel<<<(32 * NCOL + 255) / 256, 256>>>(w1, b1, w2, b2, vw, vb);

    cudaFuncSetAttribute(spatial_appnp_kernel,
                         cudaFuncAttributeMaxDynamicSharedMemorySize, SMEM_BYTES);

    spatial_appnp_kernel<<<frames, NT, SMEM_BYTES>>>(
        x, og, ob, lg, lb, aw, ab, psw, out);
}

// round 6
// speedup vs baseline: 1.6720x; 1.3721x over previous
#include <cuda_runtime.h>
#include <cuda_fp16.h>
#include <cuda_bf16.h>
#include <cstdint>

#define NJ 17
#define DM 128
#define NEDGE 49
#define NROWS 66096          // 3888 * 17
#define NFR 3888
#define MTILES 517           // ceil(66096/128)
#define NCHUNK 5             // 640 / 128
#define KSTRIDE 136          // smem row stride (bf16 elems), conflict-free ldmatrix

// ---------------- device scratch ----------------
__device__ float g_XS[(size_t)NROWS * DM];
__device__ float g_X0[(size_t)NROWS * DM];
__device__ float g_skip[NROWS];
__device__ __align__(16) __nv_bfloat16 g_ah[(size_t)MTILES * 128 * 128];
__device__ __align__(16) __nv_bfloat16 g_al[(size_t)MTILES * 128 * 128];
__device__ __align__(16) __nv_bfloat16 g_bh[640 * 128];
__device__ __align__(16) __nv_bfloat16 g_bl[640 * 128];
__device__ float g_bias[640];
__device__ __align__(16) __half g_lr[(size_t)NROWS * 512];
__device__ __align__(16) float g_v[(size_t)NROWS * DM];

// ---------------- adjacency ----------------
__device__ __constant__ int c_row_start[18] =
    {0,4,7,10,12,15,18,20,23,28,31,33,36,39,41,44,47,49};
__device__ __constant__ signed char c_nbr[NEDGE] = {
    0,1,4,7,  0,1,2,  1,2,3,  2,3,  0,4,5,  4,5,6,  5,6,  0,7,8,
    7,8,9,11,14,  8,9,10,  9,10,  8,11,12,  11,12,13,  12,13,
    8,14,15,  14,15,16,  15,16};
__device__ __constant__ signed char c_erow[NEDGE] = {
    0,0,0,0,  1,1,1,  2,2,2,  3,3,  4,4,4,  5,5,5,  6,6,  7,7,7,
    8,8,8,8,8,  9,9,9,  10,10,  11,11,11,  12,12,12,  13,13,
    14,14,14,  15,15,15,  16,16};

// ---------------- helpers ----------------
__device__ __forceinline__ uint32_t smem_u32(const void* p) {
    uint32_t a;
    asm("{ .reg .u64 t; cvta.to.shared.u64 t, %1; cvt.u32.u64 %0, t; }" : "=r"(a) : "l"(p));
    return a;
}
__device__ __forceinline__ float warp_sum(float v) {
#pragma unroll
    for (int o = 16; o; o >>= 1) v += __shfl_xor_sync(0xffffffffu, v, o);
    return v;
}
__device__ __forceinline__ void ldm4(uint32_t* r, uint32_t addr) {
    asm volatile("ldmatrix.sync.aligned.m8n8.x4.shared.b16 {%0,%1,%2,%3}, [%4];"
                 : "=r"(r[0]), "=r"(r[1]), "=r"(r[2]), "=r"(r[3]) : "r"(addr));
}
__device__ __forceinline__ void mma_bf16(float* c, const uint32_t* a, const uint32_t* b) {
    asm volatile("mma.sync.aligned.m16n8k16.row.col.f32.bf16.bf16.f32 "
                 "{%0,%1,%2,%3}, {%4,%5,%6,%7}, {%8,%9}, {%0,%1,%2,%3};"
                 : "+f"(c[0]), "+f"(c[1]), "+f"(c[2]), "+f"(c[3])
                 : "r"(a[0]), "r"(a[1]), "r"(a[2]), "r"(a[3]), "r"(b[0]), "r"(b[1]));
}

// ---------------- prologue: split weights into bf16 hi/lo, row-major [640][128] ----------------
__global__ void prep_kernel(const float* __restrict__ w1, const float* __restrict__ b1,
                            const float* __restrict__ w2, const float* __restrict__ b2,
                            const float* __restrict__ vw, const float* __restrict__ vb)
{
    int idx = blockIdx.x * blockDim.x + threadIdx.x;
    if (idx < 640 * 128) {
        int n = idx >> 7;        // global output column 0..639
        int k = idx & 127;
        float w = (n < 256) ? w1[k * 256 + n]
                : (n < 512) ? w2[k * 256 + (n - 256)]
                            : vw[k * 128 + (n - 512)];
        __nv_bfloat16 h = __float2bfloat16(w);
        __nv_bfloat16 l = __float2bfloat16(w - __bfloat162float(h));
        g_bh[idx] = h;
        g_bl[idx] = l;
    }
    if (idx < 640) {
        g_bias[idx] = (idx < 256) ? b1[idx]
                    : (idx < 512) ? b2[idx - 256]
                                  : vb[idx - 512];
    }
}

// ---------------- outer LN: x -> g_XS, g_X0 ----------------
__global__ __launch_bounds__(256) void outer_ln_kernel(
    const float* __restrict__ x,
    const float* __restrict__ og, const float* __restrict__ ob)
{
    int row = blockIdx.x * 8 + (threadIdx.x >> 5);
    int lane = threadIdx.x & 31;
    float4 v = *reinterpret_cast<const float4*>(x + (size_t)row * DM + lane * 4);
    float m = warp_sum(v.x + v.y + v.z + v.w) * (1.0f / 128.0f);
    float dx = v.x - m, dy = v.y - m, dz = v.z - m, dw = v.w - m;
    float ss = warp_sum(dx * dx + dy * dy + dz * dz + dw * dw);
    float rstd = rsqrtf(ss * (1.0f / 128.0f) + 1e-5f);
    int k = lane * 4;
    float4 o;
    o.x = dx * rstd * __ldg(og + k)     + __ldg(ob + k);
    o.y = dy * rstd * __ldg(og + k + 1) + __ldg(ob + k + 1);
    o.z = dz * rstd * __ldg(og + k + 2) + __ldg(ob + k + 2);
    o.w = dw * rstd * __ldg(og + k + 3) + __ldg(ob + k + 3);
    *reinterpret_cast<float4*>(g_XS + (size_t)row * DM + k) = o;
    *reinterpret_cast<float4*>(g_X0 + (size_t)row * DM + k) = o;
}

// ---------------- per-iter LN: g_XS -> split bf16 A rows + skip gate ----------------
__global__ __launch_bounds__(256) void ln_kernel(
    const float* __restrict__ lg, const float* __restrict__ lb,
    const float* __restrict__ aw, const float* __restrict__ ab)
{
    int row = blockIdx.x * 8 + (threadIdx.x >> 5);
    int lane = threadIdx.x & 31;
    float4 v = *reinterpret_cast<const float4*>(g_XS + (size_t)row * DM + lane * 4);
    float m = warp_sum(v.x + v.y + v.z + v.w) * (1.0f / 128.0f);
    float dx = v.x - m, dy = v.y - m, dz = v.z - m, dw = v.w - m;
    float ss = warp_sum(dx * dx + dy * dy + dz * dz + dw * dw);
    float rstd = rsqrtf(ss * (1.0f / 128.0f) + 1e-5f);
    int k = lane * 4;
    float n0 = dx * rstd * __ldg(lg + k)     + __ldg(lb + k);
    float n1 = dy * rstd * __ldg(lg + k + 1) + __ldg(lb + k + 1);
    float n2 = dz * rstd * __ldg(lg + k + 2) + __ldg(lb + k + 2);
    float n3 = dw * rstd * __ldg(lg + k + 3) + __ldg(lb + k + 3);
    float ad = warp_sum(n0 * __ldg(aw + k)     + n1 * __ldg(aw + k + 1)
                      + n2 * __ldg(aw + k + 2) + n3 * __ldg(aw + k + 3));
    if (lane == 0) g_skip[row] = 1.0f / (1.0f + __expf(-(ad + __ldg(ab))));

    __nv_bfloat16 h0 = __float2bfloat16(n0), h1 = __float2bfloat16(n1);
    __nv_bfloat16 h2 = __float2bfloat16(n2), h3 = __float2bfloat16(n3);
    __nv_bfloat162 ph01 = __halves2bfloat162(h0, h1);
    __nv_bfloat162 ph23 = __halves2bfloat162(h2, h3);
    __nv_bfloat162 pl01 = __halves2bfloat162(
        __float2bfloat16(n0 - __bfloat162float(h0)),
        __float2bfloat16(n1 - __bfloat162float(h1)));
    __nv_bfloat162 pl23 = __halves2bfloat162(
        __float2bfloat16(n2 - __bfloat162float(h2)),
        __float2bfloat16(n3 - __bfloat162float(h3)));
    uint2 uh, ul;
    uh.x = *reinterpret_cast<uint32_t*>(&ph01);
    uh.y = *reinterpret_cast<uint32_t*>(&ph23);
    ul.x = *reinterpret_cast<uint32_t*>(&pl01);
    ul.y = *reinterpret_cast<uint32_t*>(&pl23);
    *reinterpret_cast<uint2*>(g_ah + (size_t)row * 128 + k) = uh;
    *reinterpret_cast<uint2*>(g_al + (size_t)row * 128 + k) = ul;
}

// ---------------- GEMM: D[128,128] = A[128x128] @ B[128x128]^T, 3-term bf16 split ----------------
#define TILE_SM (128 * KSTRIDE)                 // bf16 elems per smem tile
#define GEMM_SMEM (4 * TILE_SM * 2)             // 139264 bytes

__global__ __launch_bounds__(256) void gemm_kernel()
{
    extern __shared__ __nv_bfloat16 sm[];
    __nv_bfloat16* sAh = sm;
    __nv_bfloat16* sAl = sm + TILE_SM;
    __nv_bfloat16* sBh = sm + 2 * TILE_SM;
    __nv_bfloat16* sBl = sm + 3 * TILE_SM;

    const int tid = threadIdx.x;
    const int mtile = blockIdx.x;
    const int chunk = blockIdx.y;

    // ---- load 4 tiles (row-major 128x128 bf16) into padded smem ----
    {
        const uint4* gAh = reinterpret_cast<const uint4*>(g_ah + (size_t)mtile * 128 * 128);
        const uint4* gAl = reinterpret_cast<const uint4*>(g_al + (size_t)mtile * 128 * 128);
        const uint4* gBh = reinterpret_cast<const uint4*>(g_bh + (size_t)chunk * 128 * 128);
        const uint4* gBl = reinterpret_cast<const uint4*>(g_bl + (size_t)chunk * 128 * 128);
        for (int i = tid; i < 2048; i += 256) {
            int row = i >> 4, c = i & 15;
            int d = row * KSTRIDE + c * 8;
            *reinterpret_cast<uint4*>(sAh + d) = gAh[i];
            *reinterpret_cast<uint4*>(sAl + d) = gAl[i];
            *reinterpret_cast<uint4*>(sBh + d) = gBh[i];
            *reinterpret_cast<uint4*>(sBl + d) = gBl[i];
        }
    }
    __syncthreads();

    const int wid = tid >> 5, lane = tid & 31;
    const int wm = wid >> 2, wn = wid & 3;       // warp tile: 64M x 32N
    const int mBase = wm * 64, nBase = wn * 32;
    const int g = lane >> 3, r = lane & 7;

    // ldmatrix per-lane addresses
    const int a_row = r + (g & 1) * 8, a_k = (g >> 1) * 8;
    const int b_n = r + (g >> 1) * 8, b_k = (g & 1) * 8;
    uint32_t aBaseH = smem_u32(sAh) + ((mBase + a_row) * KSTRIDE + a_k) * 2;
    uint32_t aBaseL = smem_u32(sAl) + ((mBase + a_row) * KSTRIDE + a_k) * 2;
    uint32_t bBaseH = smem_u32(sBh) + ((nBase + b_n) * KSTRIDE + b_k) * 2;
    uint32_t bBaseL = smem_u32(sBl) + ((nBase + b_n) * KSTRIDE + b_k) * 2;

    float acc[4][4][4];
#pragma unroll
    for (int mt = 0; mt < 4; mt++)
#pragma unroll
        for (int nt = 0; nt < 4; nt++)
#pragma unroll
            for (int q = 0; q < 4; q++) acc[mt][nt][q] = 0.f;

#pragma unroll 1
    for (int k0 = 0; k0 < 128; k0 += 16) {
        uint32_t ah[4][4], al[4][4], bh[4][2], bl[4][2];
#pragma unroll
        for (int mt = 0; mt < 4; mt++) {
            uint32_t off = (uint32_t)(mt * 16 * KSTRIDE + k0) * 2;
            ldm4(ah[mt], aBaseH + off);
            ldm4(al[mt], aBaseL + off);
        }
#pragma unroll
        for (int p = 0; p < 2; p++) {
            uint32_t off = (uint32_t)(p * 16 * KSTRIDE + k0) * 2;
            uint32_t t[4];
            ldm4(t, bBaseH + off);
            bh[2 * p][0] = t[0]; bh[2 * p][1] = t[1];
            bh[2 * p + 1][0] = t[2]; bh[2 * p + 1][1] = t[3];
            ldm4(t, bBaseL + off);
            bl[2 * p][0] = t[0]; bl[2 * p][1] = t[1];
            bl[2 * p + 1][0] = t[2]; bl[2 * p + 1][1] = t[3];
        }
#pragma unroll
        for (int mt = 0; mt < 4; mt++)
#pragma unroll
            for (int nt = 0; nt < 4; nt++) {
                mma_bf16(acc[mt][nt], ah[mt], bh[nt]);
                mma_bf16(acc[mt][nt], al[mt], bh[nt]);
                mma_bf16(acc[mt][nt], ah[mt], bl[nt]);
            }
    }

    // ---- epilogue: +bias; l,r -> fp16 g_lr; v -> fp32 g_v ----
    const int qrow = lane >> 2, qcol = (lane & 3) * 2;
#pragma unroll
    for (int mt = 0; mt < 4; mt++) {
#pragma unroll
        for (int nt = 0; nt < 4; nt++) {
            int row0 = mtile * 128 + mBase + mt * 16 + qrow;
            int col = nBase + nt * 8 + qcol;          // within this 128-chunk
            int gcol = chunk * 128 + col;
            float b0 = g_bias[gcol], b1 = g_bias[gcol + 1];
            float c0 = acc[mt][nt][0] + b0, c1 = acc[mt][nt][1] + b1;
            float c2 = acc[mt][nt][2] + b0, c3 = acc[mt][nt][3] + b1;
            if (chunk < 4) {
                if (row0 < NROWS)
                    *reinterpret_cast<__half2*>(&g_lr[(size_t)row0 * 512 + gcol]) =
                        __halves2half2(__float2half(c0), __float2half(c1));
                if (row0 + 8 < NROWS)
                    *reinterpret_cast<__half2*>(&g_lr[(size_t)(row0 + 8) * 512 + gcol]) =
                        __halves2half2(__float2half(c2), __float2half(c3));
            } else {
                if (row0 < NROWS) {
                    float2 o; o.x = c0; o.y = c1;
                    *reinterpret_cast<float2*>(&g_v[(size_t)row0 * DM + col]) = o;
                }
                if (row0 + 8 < NROWS) {
                    float2 o; o.x = c2; o.y = c3;
                    *reinterpret_cast<float2*>(&g_v[(size_t)(row0 + 8) * DM + col]) = o;
                }
            }
        }
    }
}

// ---------------- attention: scores + softmax + aggregate + gelu + mix ----------------
__global__ __launch_bounds__(128) void attn_kernel(const float* __restrict__ psw,
                                                   float* __restrict__ dst)
{
    __shared__ __align__(16) __half LR[NJ * 512];
    __shared__ __align__(16) float V[NJ * DM];
    __shared__ float SC[2 * NEDGE];
    __shared__ float SK[NJ];
    __shared__ float PSW[DM];

    const int tid = threadIdx.x;
    const int wid = tid >> 5;
    const int lane = tid & 31;
    const size_t r0 = (size_t)blockIdx.x * NJ;

    {
        const uint4* src = reinterpret_cast<const uint4*>(g_lr + r0 * 512);
        uint4* d = reinterpret_cast<uint4*>(LR);
        for (int i = tid; i < NJ * 512 * 2 / 16; i += 128) d[i] = src[i];
        const uint4* sv = reinterpret_cast<const uint4*>(g_v + r0 * DM);
        uint4* dv = reinterpret_cast<uint4*>(V);
        for (int i = tid; i < NJ * DM * 4 / 16; i += 128) dv[i] = sv[i];
    }
    if (tid < NJ) SK[tid] = g_skip[r0 + tid];
    if (tid < DM) PSW[tid] = psw[tid];
    __syncthreads();

    for (int t = wid; t < 2 * NEDGE; t += 4) {
        int h = (t >= NEDGE);
        int e = t - h * NEDGE;
        int i = c_erow[e];
        int j = c_nbr[e];
        const __half* lp = LR + i * 512 + h * 128;
        const __half* rp = LR + j * 512 + 256 + h * 128;
        float acc = 0.f;
#pragma unroll
        for (int q = 0; q < 4; q++) {
            int d = lane + 32 * q;
            float u = __half2float(lp[d]) + __half2float(rp[d]);
            acc = fmaf(fmaxf(u, 0.2f * u), PSW[d], acc);
        }
        acc = warp_sum(acc);
        if (lane == 0) SC[t] = acc;
    }
    __syncthreads();

    if (tid < 34) {
        int h = (tid >= NJ);
        int i = tid - h * NJ;
        int rs = c_row_start[i], re = c_row_start[i + 1];
        float m = -1e30f;
        for (int e = rs; e < re; e++) m = fmaxf(m, SC[h * NEDGE + e]);
        float s = 0.f;
        for (int e = rs; e < re; e++) s += __expf(SC[h * NEDGE + e] - m);
        float inv = 1.0f / s;
        for (int e = rs; e < re; e++)
            SC[h * NEDGE + e] = __expf(SC[h * NEDGE + e] - m) * inv;
    }
    __syncthreads();

    for (int idx = tid; idx < NJ * DM; idx += 128) {
        int j = idx >> 7, c = idx & 127;
        int h = c >> 6, d = c & 63;
        int rs = c_row_start[j], re = c_row_start[j + 1];
        float acc = 0.f;
        for (int e = rs; e < re; e++)
            acc = fmaf(SC[h * NEDGE + e], V[(int)c_nbr[e] * DM + h * 64 + d], acc);
        float gl = 0.5f * acc * (1.0f + erff(acc * 0.70710678118654752f));
        float sk = SK[j];
        dst[r0 * DM + idx] = (1.0f - sk) * gl + sk * g_X0[r0 * DM + idx];
    }
}

// ---------------- launch ----------------
extern "C" void kernel_launch(void* const* d_in, const int* in_sizes, int n_in,
                              void* d_out, int out_size) {
    const float* x   = (const float*)d_in[0];
    const float* og  = (const float*)d_in[1];
    const float* ob  = (const float*)d_in[2];
    const float* lg  = (const float*)d_in[3];
    const float* lb  = (const float*)d_in[4];
    const float* aw  = (const float*)d_in[5];
    const float* ab  = (const float*)d_in[6];
    const float* w1  = (const float*)d_in[7];
    const float* b1  = (const float*)d_in[8];
    const float* w2  = (const float*)d_in[9];
    const float* b2  = (const float*)d_in[10];
    const float* psw = (const float*)d_in[11];
    const float* vw  = (const float*)d_in[13];
    const float* vb  = (const float*)d_in[14];
    float* out = (float*)d_out;

    cudaFuncSetAttribute(gemm_kernel,
                         cudaFuncAttributeMaxDynamicSharedMemorySize, GEMM_SMEM);

    prep_kernel<<<(640 * 128 + 255) / 256, 256>>>(w1, b1, w2, b2, vw, vb);
    outer_ln_kernel<<<NROWS / 8, 256>>>(x, og, ob);

    float* g_xs_ptr = nullptr;
    cudaGetSymbolAddress((void**)&g_xs_ptr, g_XS);

    for (int it = 0; it < 4; it++) {
        ln_kernel<<<NROWS / 8, 256>>>(lg, lb, aw, ab);
        gemm_kernel<<<dim3(MTILES, NCHUNK), 256, GEMM_SMEM>>>();
        attn_kernel<<<NFR, 128>>>(psw, (it == 3) ? out : g_xs_ptr);
    }
}